// round 2
// baseline (speedup 1.0000x reference)
#include <cuda_runtime.h>

#define N_NODES   50000
#define N_EDGES   800000
#define IN_DIM    1280
#define HID       512
#define EMB       64
#define LN_EPS    1e-5f
#define NEG_SLOPE 0.2f

// ---------------- scratch (static device globals; no allocation) ----------------
__device__ float g_feat[N_NODES * EMB];   // 12.8 MB
__device__ float g_el[N_NODES];
__device__ float g_er[N_NODES];
__device__ float g_m[N_NODES];
__device__ float g_s[N_NODES];
__device__ float g_e[N_EDGES];            // 3.2 MB

constexpr int BM = 32;          // nodes per block
constexpr int BK = 32;          // K tile
constexpr int XS = HID + 4;     // padded stride for LN'd row in smem (bank-spread)

// =================================================================================
// Kernel 1: x = LN(ReLU(features@W1 + b1)); feat = x@Wg; el = feat@attn_l; er = feat@attn_r
// One block = 32 nodes. Phase 1: tiled fp32 GEMM (full 512-wide row per block so
// LayerNorm fuses in-register). Phase 2: GEMM2 from smem with Wg streamed via L1.
// =================================================================================
__global__ __launch_bounds__(256) void node_kernel(
    const float* __restrict__ A,   const float* __restrict__ W1,
    const float* __restrict__ b1,  const float* __restrict__ ln_g,
    const float* __restrict__ ln_b,const float* __restrict__ Wg,
    const float* __restrict__ attn_l, const float* __restrict__ attn_r)
{
    extern __shared__ float Bs[];           // phase1: [BK][HID] flat (16384 f); phase2: XN [BM][XS] (16512 f)
    __shared__ float As[BM][BK + 4];

    const int tid   = threadIdx.x;
    const int warp  = tid >> 5;
    const int lane  = tid & 31;
    const int node0 = blockIdx.x * BM;

    float acc[4][16];
#pragma unroll
    for (int r = 0; r < 4; r++)
#pragma unroll
        for (int j = 0; j < 16; j++) acc[r][j] = 0.f;

    // A-tile load mapping: thread -> (row, 4 consecutive k)
    const int  lr     = tid >> 3;         // 0..31
    const int  lk     = (tid & 7) * 4;    // 0,4,...,28
    const int  arow   = node0 + lr;
    const bool avalid = arow < N_NODES;
    const float* Aptr = A + (size_t)arow * IN_DIM;

    for (int k0 = 0; k0 < IN_DIM; k0 += BK) {
        float4 av = make_float4(0.f, 0.f, 0.f, 0.f);
        if (avalid) av = *(const float4*)(Aptr + k0 + lk);
        As[lr][lk + 0] = av.x; As[lr][lk + 1] = av.y;
        As[lr][lk + 2] = av.z; As[lr][lk + 3] = av.w;

        // W1 tile: 32 x 512 floats, 16 float4 per thread, fully coalesced
#pragma unroll
        for (int p = 0; p < 16; p++) {
            int idx = p * 1024 + tid * 4;
            int kr = idx >> 9, c = idx & 511;
            *(float4*)&Bs[kr * HID + c] =
                *(const float4*)(W1 + (size_t)(k0 + kr) * HID + c);
        }
        __syncthreads();

#pragma unroll 8
        for (int kk = 0; kk < BK; kk++) {
            const float a0 = As[warp * 4 + 0][kk];
            const float a1 = As[warp * 4 + 1][kk];
            const float a2 = As[warp * 4 + 2][kk];
            const float a3 = As[warp * 4 + 3][kk];
#pragma unroll
            for (int j = 0; j < 16; j++) {
                const float bv = Bs[kk * HID + lane + 32 * j];
                acc[0][j] = fmaf(a0, bv, acc[0][j]);
                acc[1][j] = fmaf(a1, bv, acc[1][j]);
                acc[2][j] = fmaf(a2, bv, acc[2][j]);
                acc[3][j] = fmaf(a3, bv, acc[3][j]);
            }
        }
        __syncthreads();
    }

    // ---- bias + ReLU + LayerNorm; write normalized rows into smem (reuse Bs) ----
    float gg[16], bb[16], bias[16];
#pragma unroll
    for (int j = 0; j < 16; j++) {
        const int c = lane + 32 * j;
        gg[j] = ln_g[c]; bb[j] = ln_b[c]; bias[j] = b1[c];
    }
#pragma unroll
    for (int r = 0; r < 4; r++) {
        float sum = 0.f, sq = 0.f;
#pragma unroll
        for (int j = 0; j < 16; j++) {
            float v = acc[r][j] + bias[j];
            v = v > 0.f ? v : 0.f;
            acc[r][j] = v;
            sum += v;
            sq = fmaf(v, v, sq);
        }
#pragma unroll
        for (int o = 16; o >= 1; o >>= 1) {
            sum += __shfl_xor_sync(0xffffffffu, sum, o);
            sq  += __shfl_xor_sync(0xffffffffu, sq,  o);
        }
        const float mu   = sum * (1.f / HID);
        const float var  = sq * (1.f / HID) - mu * mu;
        const float rstd = rsqrtf(var + LN_EPS);
        const int   row  = warp * 4 + r;
#pragma unroll
        for (int j = 0; j < 16; j++) {
            const float xn = (acc[r][j] - mu) * rstd * gg[j] + bb[j];
            Bs[row * XS + lane + 32 * j] = xn;
        }
    }
    __syncthreads();

    // ---- Phase 2: feat = xn @ Wg  (thread -> 1 row x 8 cols), then el/er ----
    const int prow = tid >> 3;            // 0..31
    const int c0   = (tid & 7) * 8;       // 0..56
    float f[8];
#pragma unroll
    for (int i = 0; i < 8; i++) f[i] = 0.f;

#pragma unroll 4
    for (int k = 0; k < HID; k++) {
        const float  xv = Bs[prow * XS + k];
        const float4 w0 = *(const float4*)(Wg + (size_t)k * EMB + c0);
        const float4 w1 = *(const float4*)(Wg + (size_t)k * EMB + c0 + 4);
        f[0] = fmaf(xv, w0.x, f[0]); f[1] = fmaf(xv, w0.y, f[1]);
        f[2] = fmaf(xv, w0.z, f[2]); f[3] = fmaf(xv, w0.w, f[3]);
        f[4] = fmaf(xv, w1.x, f[4]); f[5] = fmaf(xv, w1.y, f[5]);
        f[6] = fmaf(xv, w1.z, f[6]); f[7] = fmaf(xv, w1.w, f[7]);
    }

    float elp = 0.f, erp = 0.f;
#pragma unroll
    for (int i = 0; i < 8; i++) {
        elp = fmaf(f[i], attn_l[c0 + i], elp);
        erp = fmaf(f[i], attn_r[c0 + i], erp);
    }
#pragma unroll
    for (int o = 4; o >= 1; o >>= 1) {
        elp += __shfl_down_sync(0xffffffffu, elp, o);
        erp += __shfl_down_sync(0xffffffffu, erp, o);
    }

    const int gnode = node0 + prow;
    if (gnode < N_NODES) {
        *(float4*)(g_feat + (size_t)gnode * EMB + c0)     = make_float4(f[0], f[1], f[2], f[3]);
        *(float4*)(g_feat + (size_t)gnode * EMB + c0 + 4) = make_float4(f[4], f[5], f[6], f[7]);
        if ((tid & 7) == 0) { g_el[gnode] = elp; g_er[gnode] = erp; }
    }
}

// ============================== Kernel 2: init ===================================
__global__ void init_kernel(float* __restrict__ out, const float* __restrict__ bias_g)
{
    const int i = blockIdx.x * blockDim.x + threadIdx.x;
    if (i < N_NODES * EMB) out[i] = bias_g[i & (EMB - 1)];
    if (i < N_NODES) { g_m[i] = __int_as_float(0xff800000); g_s[i] = 0.f; }
}

// =============== Kernel 3: edge score + segment max (float atomicMax) ===========
__global__ void edge_max_kernel(const int* __restrict__ src, const int* __restrict__ dst)
{
    const int i = blockIdx.x * blockDim.x + threadIdx.x;
    if (i >= N_EDGES) return;
    float v = g_el[src[i]] + g_er[dst[i]];
    v = v > 0.f ? v : NEG_SLOPE * v;
    g_e[i] = v;
    float* addr = &g_m[dst[i]];
    // monotone int/uint encoding: works mixed-sign with -inf init
    if (v >= 0.f) atomicMax((int*)addr, __float_as_int(v));
    else          atomicMin((unsigned int*)addr, __float_as_uint(v));
}

// =============== Kernel 4: exp + segment sum =====================================
__global__ void edge_exp_kernel(const int* __restrict__ dst)
{
    const int i = blockIdx.x * blockDim.x + threadIdx.x;
    if (i >= N_EDGES) return;
    const int d = dst[i];
    const float ex = __expf(g_e[i] - g_m[d]);
    g_e[i] = ex;
    atomicAdd(&g_s[d], ex);
}

// =============== Kernel 5: weighted scatter-aggregate (warp per edge) ============
__global__ void agg_kernel(const int* __restrict__ src, const int* __restrict__ dst,
                           float* __restrict__ out)
{
    const int w    = (blockIdx.x * blockDim.x + threadIdx.x) >> 5;
    const int lane = threadIdx.x & 31;
    if (w >= N_EDGES) return;
    const int sN = src[w], dN = dst[w];
    const float a  = g_e[w] / g_s[dN];
    const float v0 = g_feat[(size_t)sN * EMB + lane]      * a;
    const float v1 = g_feat[(size_t)sN * EMB + 32 + lane] * a;
    atomicAdd(out + (size_t)dN * EMB + lane,      v0);
    atomicAdd(out + (size_t)dN * EMB + 32 + lane, v1);
}

// =================================================================================
extern "C" void kernel_launch(void* const* d_in, const int* in_sizes, int n_in,
                              void* d_out, int out_size)
{
    const float* features = (const float*)d_in[0];
    const int*   src      = (const int*)  d_in[1];
    const int*   dst      = (const int*)  d_in[2];
    const float* W1       = (const float*)d_in[3];
    const float* b1       = (const float*)d_in[4];
    const float* ln_g     = (const float*)d_in[5];
    const float* ln_b     = (const float*)d_in[6];
    const float* Wg       = (const float*)d_in[7];
    const float* attn_l   = (const float*)d_in[8];
    const float* attn_r   = (const float*)d_in[9];
    const float* bias_g   = (const float*)d_in[10];
    float* out = (float*)d_out;

    const size_t smem = (size_t)BM * XS * sizeof(float);   // 66048 B (> 48KB: opt in)
    cudaFuncSetAttribute(node_kernel, cudaFuncAttributeMaxDynamicSharedMemorySize, (int)smem);

    node_kernel<<<(N_NODES + BM - 1) / BM, 256, smem>>>(
        features, W1, b1, ln_g, ln_b, Wg, attn_l, attn_r);

    init_kernel<<<(N_NODES * EMB + 255) / 256, 256>>>(out, bias_g);

    edge_max_kernel<<<(N_EDGES + 255) / 256, 256>>>(src, dst);
    edge_exp_kernel<<<(N_EDGES + 255) / 256, 256>>>(dst);

    // one warp per edge
    const long long agg_threads = (long long)N_EDGES * 32;
    agg_kernel<<<(int)((agg_threads + 255) / 256), 256>>>(src, dst, out);
}

// round 4
// speedup vs baseline: 4.6146x; 4.6146x over previous
#include <cuda_runtime.h>
#include <cuda_bf16.h>
#include <cstdint>

#define N_NODES   50000
#define N_EDGES   800000
#define IN_DIM    1280
#define HID       512
#define EMB       64
#define LN_EPS    1e-5f
#define NEG_SLOPE 0.2f

// ---------------- scratch (static device globals; no allocation) ----------------
__device__ float g_feat[N_NODES * EMB];
__device__ float g_el[N_NODES];
__device__ float g_er[N_NODES];
__device__ float g_m[N_NODES];
__device__ float g_s[N_NODES];
__device__ float g_e[N_EDGES];
// W1^T bf16 hi/lo, tiled layout: [kt][n][16] with k = kt*16+kk  (kt: 0..79)
__device__ __align__(16) __nv_bfloat16 g_w1h[IN_DIM * HID];
__device__ __align__(16) __nv_bfloat16 g_w1l[IN_DIM * HID];
// (ln_g .* Wg) bf16 hi/lo, layout [n][k] (n-major, k contiguous)
__device__ __align__(16) __nv_bfloat16 g_wg2h[HID * EMB];
__device__ __align__(16) __nv_bfloat16 g_wg2l[HID * EMB];
__device__ float g_u[EMB];   // sum_k ln_g[k]*Wg[k][j]
__device__ float g_v[EMB];   // sum_k ln_b[k]*Wg[k][j]

// =============================== helpers ========================================
__device__ __forceinline__ uint32_t s2u(const void* p) {
    uint32_t a;
    asm("{ .reg .u64 t; cvta.to.shared.u64 t, %1; cvt.u32.u64 %0, t; }" : "=r"(a) : "l"(p));
    return a;
}
__device__ __forceinline__ uint32_t pack_bf16(float x, float y) {
    __nv_bfloat162 t;
    t.x = __float2bfloat16_rn(x);
    t.y = __float2bfloat16_rn(y);
    return *reinterpret_cast<uint32_t*>(&t);
}

#define LDM4(R, addr) \
    asm volatile("ldmatrix.sync.aligned.m8n8.x4.shared.b16 {%0,%1,%2,%3}, [%4];" \
        : "=r"((R)[0]), "=r"((R)[1]), "=r"((R)[2]), "=r"((R)[3]) : "r"(addr))

#define MMA(C, A_, B_) \
    asm volatile("mma.sync.aligned.m16n8k16.row.col.f32.bf16.bf16.f32 " \
        "{%0,%1,%2,%3},{%4,%5,%6,%7},{%8,%9},{%0,%1,%2,%3};" \
        : "+f"((C)[0]), "+f"((C)[1]), "+f"((C)[2]), "+f"((C)[3]) \
        : "r"((A_)[0]), "r"((A_)[1]), "r"((A_)[2]), "r"((A_)[3]), \
          "r"((B_)[0]), "r"((B_)[1]))

// ============================ smem layout (bytes) ================================
static constexpr int SM_B1  = 0;      // 512 f
static constexpr int SM_ATL = 2048;   // 64 f each
static constexpr int SM_ATR = 2304;
static constexpr int SM_U   = 2560;
static constexpr int SM_V   = 2816;
static constexpr int SM_SUM = 3072;
static constexpr int SM_SQ  = 3328;
static constexpr int SM_EL  = 3584;
static constexpr int SM_ER  = 3840;
static constexpr int SM_AH  = 4096;   // 64 rows x 48B (16 bf16 + pad)
static constexpr int SM_AL  = 7168;
static constexpr int SM_BH  = 10240;  // 512 rows x 48B
static constexpr int SM_BL  = 34816;
static constexpr int SM_XH  = 59392;  // 64 rows x 144B (64 bf16 + pad)
static constexpr int SM_XL  = 68608;
static constexpr int SM_B2H = 77824;  // 64 rows x 144B
static constexpr int SM_B2L = 87040;
static constexpr int SM_TOTAL = 96256;

static constexpr int K_STEPS = IN_DIM / 16;   // 80

// =================================================================================
// node_kernel: 64 nodes/CTA, 512 threads (16 warps).
// GEMM1 (HMMA bf16 hi/lo split, fp32 acc): x = F@W1 -> 64x512 in regs.
// bias+relu in-reg, LN stats via smem atomics, LN folded to post-GEMM2 affine.
// GEMM2 (HMMA): y = relu_x @ (g.*Wg), chunked k=64 through smem.
// feat = rstd*y - rstd*mu*u + v; el/er dot products; write g_feat/g_el/g_er.
// =================================================================================
__global__ __launch_bounds__(512, 1) void node_kernel(
    const float* __restrict__ A, const float* __restrict__ b1,
    const float* __restrict__ attn_l, const float* __restrict__ attn_r)
{
    extern __shared__ char smem[];
    const int tid  = threadIdx.x;
    const int lane = tid & 31;
    const int warp = tid >> 5;
    const int wm   = warp >> 3;        // GEMM1: 2 x 8 warp grid
    const int wn   = warp & 7;
    const int wm2  = warp >> 2;        // GEMM2: 4 x 4 warp grid
    const int wn2  = warp & 3;
    const int node0 = blockIdx.x * 64;

    float* sb1  = (float*)(smem + SM_B1);
    float* satl = (float*)(smem + SM_ATL);
    float* satr = (float*)(smem + SM_ATR);
    float* ssu  = (float*)(smem + SM_U);
    float* ssv  = (float*)(smem + SM_V);
    float* sSum = (float*)(smem + SM_SUM);
    float* sSq  = (float*)(smem + SM_SQ);
    float* sEl  = (float*)(smem + SM_EL);
    float* sEr  = (float*)(smem + SM_ER);

    if (tid < HID) sb1[tid] = b1[tid];
    if (tid < EMB) {
        satl[tid] = attn_l[tid]; satr[tid] = attn_r[tid];
        ssu[tid]  = g_u[tid];    ssv[tid]  = g_v[tid];
        sSum[tid] = 0.f; sSq[tid] = 0.f; sEl[tid] = 0.f; sEr[tid] = 0.f;
    }

    // accumulators: acc[(fm*8+fnn)*4 + e]
    float acc[64];
#pragma unroll
    for (int i = 0; i < 64; i++) acc[i] = 0.f;

    // ---- GEMM1 global-load mapping ----
    const int  arow = tid >> 3;            // 0..63
    const bool avalid = (node0 + arow) < N_NODES;
    const float* Ap = A + (size_t)(node0 + arow) * IN_DIM + (tid & 7) * 2;

    float2 areg = make_float2(0.f, 0.f);
    uint4  bh0, bh1, bl0, bl1;
    {
        if (avalid) areg = *(const float2*)Ap;
        const uint4* ph = (const uint4*)(g_w1h + (size_t)tid * 16);
        const uint4* pl = (const uint4*)(g_w1l + (size_t)tid * 16);
        bh0 = ph[0]; bh1 = ph[1]; bl0 = pl[0]; bl1 = pl[1];
    }

    // ---- ldmatrix lane addresses (GEMM1) ----
    const int j  = lane >> 3;
    const int l7 = lane & 7;
    const uint32_t sAHu = s2u(smem + SM_AH), sALu = s2u(smem + SM_AL);
    const uint32_t sBHu = s2u(smem + SM_BH), sBLu = s2u(smem + SM_BL);
    const uint32_t aOff = (uint32_t)((wm * 32 + (j & 1) * 8 + l7) * 48 + (j >> 1) * 16);
    const uint32_t bOff = (uint32_t)((wn * 64 + (j >> 1) * 8 + l7) * 48 + (j & 1) * 16);
    const uint32_t aAH = sAHu + aOff, aAL = sALu + aOff;
    const uint32_t aBH = sBHu + bOff, aBL = sBLu + bOff;

    __syncthreads();

    // ============================ GEMM1 main loop ================================
    for (int kt = 0; kt < K_STEPS; kt++) {
        // store prefetched tiles
        {
            const float hx = __bfloat162float(__float2bfloat16_rn(areg.x));
            const float hy = __bfloat162float(__float2bfloat16_rn(areg.y));
            const int ao = arow * 48 + (tid & 7) * 4;
            *(uint32_t*)(smem + SM_AH + ao) = pack_bf16(hx, hy);
            *(uint32_t*)(smem + SM_AL + ao) = pack_bf16(areg.x - hx, areg.y - hy);
            const int bo = tid * 48;
            *(uint4*)(smem + SM_BH + bo)      = bh0;
            *(uint4*)(smem + SM_BH + bo + 16) = bh1;
            *(uint4*)(smem + SM_BL + bo)      = bl0;
            *(uint4*)(smem + SM_BL + bo + 16) = bl1;
        }
        __syncthreads();

        // prefetch next tile (overlaps with MMA below)
        if (kt + 1 < K_STEPS) {
            if (avalid) areg = *(const float2*)(Ap + (kt + 1) * 16);
            const uint4* ph = (const uint4*)(g_w1h + (size_t)(kt + 1) * 8192 + (size_t)tid * 16);
            const uint4* pl = (const uint4*)(g_w1l + (size_t)(kt + 1) * 8192 + (size_t)tid * 16);
            bh0 = ph[0]; bh1 = ph[1]; bl0 = pl[0]; bl1 = pl[1];
        }

        // ldmatrix + mma (split: hh + hl + lh)
        uint32_t Ah[8], Al[8];
        LDM4(&Ah[0], aAH); LDM4(&Ah[4], aAH + 768);
        LDM4(&Al[0], aAL); LDM4(&Al[4], aAL + 768);
#pragma unroll
        for (int half = 0; half < 2; half++) {
            uint32_t Bh[8], Bl[8];
            LDM4(&Bh[0], aBH + half * 1536);
            LDM4(&Bh[4], aBH + half * 1536 + 768);
            LDM4(&Bl[0], aBL + half * 1536);
            LDM4(&Bl[4], aBL + half * 1536 + 768);
#pragma unroll
            for (int fm = 0; fm < 2; fm++) {
#pragma unroll
                for (int f = 0; f < 4; f++) {
                    float* C = &acc[((fm * 8) + (half * 4) + f) * 4];
                    MMA(C, &Ah[fm * 4], &Bh[f * 2]);
                    MMA(C, &Ah[fm * 4], &Bl[f * 2]);
                    MMA(C, &Al[fm * 4], &Bh[f * 2]);
                }
            }
        }
        __syncthreads();
    }

    // ================== bias + ReLU + LN stats (in-register) ====================
    {
        float ps[4] = {0.f, 0.f, 0.f, 0.f};
        float pq[4] = {0.f, 0.f, 0.f, 0.f};
#pragma unroll
        for (int fm = 0; fm < 2; fm++) {
#pragma unroll
            for (int fnn = 0; fnn < 8; fnn++) {
                const int cb = wn * 64 + fnn * 8 + (lane & 3) * 2;
                const float bv0 = sb1[cb], bv1 = sb1[cb + 1];
                float* C = &acc[(fm * 8 + fnn) * 4];
                C[0] = fmaxf(C[0] + bv0, 0.f);
                C[1] = fmaxf(C[1] + bv1, 0.f);
                C[2] = fmaxf(C[2] + bv0, 0.f);
                C[3] = fmaxf(C[3] + bv1, 0.f);
                ps[fm * 2 + 0] += C[0] + C[1];
                pq[fm * 2 + 0] = fmaf(C[0], C[0], fmaf(C[1], C[1], pq[fm * 2 + 0]));
                ps[fm * 2 + 1] += C[2] + C[3];
                pq[fm * 2 + 1] = fmaf(C[2], C[2], fmaf(C[3], C[3], pq[fm * 2 + 1]));
            }
        }
#pragma unroll
        for (int i = 0; i < 4; i++) {
            ps[i] += __shfl_xor_sync(0xffffffffu, ps[i], 1);
            ps[i] += __shfl_xor_sync(0xffffffffu, ps[i], 2);
            pq[i] += __shfl_xor_sync(0xffffffffu, pq[i], 1);
            pq[i] += __shfl_xor_sync(0xffffffffu, pq[i], 2);
        }
        if ((lane & 3) == 0) {
            const int r = wm * 32 + (lane >> 2);
            atomicAdd(&sSum[r],      ps[0]); atomicAdd(&sSq[r],      pq[0]);
            atomicAdd(&sSum[r + 8],  ps[1]); atomicAdd(&sSq[r + 8],  pq[1]);
            atomicAdd(&sSum[r + 16], ps[2]); atomicAdd(&sSq[r + 16], pq[2]);
            atomicAdd(&sSum[r + 24], ps[3]); atomicAdd(&sSq[r + 24], pq[3]);
        }
    }

    // =========================== GEMM2 (chunked k=64) ===========================
    float acc2[8];
#pragma unroll
    for (int i = 0; i < 8; i++) acc2[i] = 0.f;

    const uint32_t xOff  = (uint32_t)((wm2 * 16 + (j & 1) * 8 + l7) * 144 + (j >> 1) * 16);
    const uint32_t b2Off = (uint32_t)((wn2 * 16 + (j >> 1) * 8 + l7) * 144 + (j & 1) * 16);
    const uint32_t aXH  = s2u(smem + SM_XH)  + xOff;
    const uint32_t aXL  = s2u(smem + SM_XL)  + xOff;
    const uint32_t aB2H = s2u(smem + SM_B2H) + b2Off;
    const uint32_t aB2L = s2u(smem + SM_B2L) + b2Off;

    for (int c = 0; c < 8; c++) {
        __syncthreads();
        // owner warps write their x chunk (cols 64c..64c+63) as bf16 hi/lo
        if (wn == c) {
#pragma unroll
            for (int fm = 0; fm < 2; fm++) {
#pragma unroll
                for (int fnn = 0; fnn < 8; fnn++) {
                    const float* C = &acc[(fm * 8 + fnn) * 4];
                    const int r  = wm * 32 + fm * 16 + (lane >> 2);
                    const int cc = fnn * 8 + (lane & 3) * 2;
                    {
                        const float hx = __bfloat162float(__float2bfloat16_rn(C[0]));
                        const float hy = __bfloat162float(__float2bfloat16_rn(C[1]));
                        *(uint32_t*)(smem + SM_XH + r * 144 + cc * 2) = pack_bf16(hx, hy);
                        *(uint32_t*)(smem + SM_XL + r * 144 + cc * 2) = pack_bf16(C[0] - hx, C[1] - hy);
                    }
                    {
                        const float hx = __bfloat162float(__float2bfloat16_rn(C[2]));
                        const float hy = __bfloat162float(__float2bfloat16_rn(C[3]));
                        *(uint32_t*)(smem + SM_XH + (r + 8) * 144 + cc * 2) = pack_bf16(hx, hy);
                        *(uint32_t*)(smem + SM_XL + (r + 8) * 144 + cc * 2) = pack_bf16(C[2] - hx, C[3] - hy);
                    }
                }
            }
        }
        // all threads: copy wg2 chunk [64 n-rows x 64 k] hi/lo to smem
        {
            const int n  = tid >> 3;
            const int k8 = (tid & 7) * 8;
            const uint4 h = *(const uint4*)(g_wg2h + (size_t)n * HID + c * 64 + k8);
            const uint4 l = *(const uint4*)(g_wg2l + (size_t)n * HID + c * 64 + k8);
            *(uint4*)(smem + SM_B2H + n * 144 + k8 * 2) = h;
            *(uint4*)(smem + SM_B2L + n * 144 + k8 * 2) = l;
        }
        __syncthreads();

#pragma unroll
        for (int ck = 0; ck < 4; ck++) {
            uint32_t XH[4], XL[4], BH2[4], BL2[4];
            LDM4(XH,  aXH  + ck * 32);
            LDM4(XL,  aXL  + ck * 32);
            LDM4(BH2, aB2H + ck * 32);
            LDM4(BL2, aB2L + ck * 32);
            MMA(&acc2[0], XH, &BH2[0]);
            MMA(&acc2[0], XH, &BL2[0]);
            MMA(&acc2[0], XL, &BH2[0]);
            MMA(&acc2[4], XH, &BH2[2]);
            MMA(&acc2[4], XH, &BL2[2]);
            MMA(&acc2[4], XL, &BH2[2]);
        }
    }

    // ============================ epilogue =======================================
    {
        const int r0 = wm2 * 16 + (lane >> 2);
        const int r1 = r0 + 8;
        const float mu0 = sSum[r0] * (1.f / HID);
        const float v0  = sSq[r0] * (1.f / HID) - mu0 * mu0;
        const float rs0 = rsqrtf(v0 + LN_EPS);
        const float rm0 = rs0 * mu0;
        const float mu1 = sSum[r1] * (1.f / HID);
        const float v1  = sSq[r1] * (1.f / HID) - mu1 * mu1;
        const float rs1 = rsqrtf(v1 + LN_EPS);
        const float rm1 = rs1 * mu1;

        const bool ok0 = (node0 + r0) < N_NODES;
        const bool ok1 = (node0 + r1) < N_NODES;

        float el0 = 0.f, er0 = 0.f, el1 = 0.f, er1 = 0.f;
#pragma unroll
        for (int fn2 = 0; fn2 < 2; fn2++) {
            const int cb = wn2 * 16 + fn2 * 8 + (lane & 3) * 2;
            const float uA = ssu[cb], uB = ssu[cb + 1];
            const float vA = ssv[cb], vB = ssv[cb + 1];
            const float lA = satl[cb], lB = satl[cb + 1];
            const float rA = satr[cb], rB = satr[cb + 1];
            const float* Y = &acc2[fn2 * 4];
            const float f00 = rs0 * Y[0] - rm0 * uA + vA;
            const float f01 = rs0 * Y[1] - rm0 * uB + vB;
            const float f10 = rs1 * Y[2] - rm1 * uA + vA;
            const float f11 = rs1 * Y[3] - rm1 * uB + vB;
            if (ok0) *(float2*)(g_feat + (size_t)(node0 + r0) * EMB + cb) = make_float2(f00, f01);
            if (ok1) *(float2*)(g_feat + (size_t)(node0 + r1) * EMB + cb) = make_float2(f10, f11);
            el0 = fmaf(f00, lA, fmaf(f01, lB, el0));
            er0 = fmaf(f00, rA, fmaf(f01, rB, er0));
            el1 = fmaf(f10, lA, fmaf(f11, lB, el1));
            er1 = fmaf(f10, rA, fmaf(f11, rB, er1));
        }
        el0 += __shfl_xor_sync(0xffffffffu, el0, 1); el0 += __shfl_xor_sync(0xffffffffu, el0, 2);
        er0 += __shfl_xor_sync(0xffffffffu, er0, 1); er0 += __shfl_xor_sync(0xffffffffu, er0, 2);
        el1 += __shfl_xor_sync(0xffffffffu, el1, 1); el1 += __shfl_xor_sync(0xffffffffu, el1, 2);
        er1 += __shfl_xor_sync(0xffffffffu, er1, 1); er1 += __shfl_xor_sync(0xffffffffu, er1, 2);
        if ((lane & 3) == 0) {
            atomicAdd(&sEl[r0], el0); atomicAdd(&sEr[r0], er0);
            atomicAdd(&sEl[r1], el1); atomicAdd(&sEr[r1], er1);
        }
    }
    __syncthreads();
    if (tid < 64 && node0 + tid < N_NODES) {
        g_el[node0 + tid] = sEl[tid];
        g_er[node0 + tid] = sEr[tid];
    }
}

// ============================ precompute kernels =================================
__global__ void prep_w1(const float* __restrict__ W1)
{
    const int i = blockIdx.x * blockDim.x + threadIdx.x;
    if (i >= IN_DIM * HID) return;
    const int kt = i >> 13;           // / 8192
    const int rem = i & 8191;
    const int n = rem >> 4, kk = rem & 15;
    const int k = kt * 16 + kk;
    const float w = W1[(size_t)k * HID + n];
    const __nv_bfloat16 h = __float2bfloat16_rn(w);
    g_w1h[i] = h;
    g_w1l[i] = __float2bfloat16_rn(w - __bfloat162float(h));
}
__global__ void prep_wg(const float* __restrict__ Wg, const float* __restrict__ ln_g)
{
    const int i = blockIdx.x * blockDim.x + threadIdx.x;
    if (i >= HID * EMB) return;
    const int n = i >> 9, k = i & 511;    // [n][k]
    const float w = ln_g[k] * Wg[(size_t)k * EMB + n];
    const __nv_bfloat16 h = __float2bfloat16_rn(w);
    g_wg2h[i] = h;
    g_wg2l[i] = __float2bfloat16_rn(w - __bfloat162float(h));
}
__global__ void prep_uv(const float* __restrict__ Wg, const float* __restrict__ ln_g,
                        const float* __restrict__ ln_b)
{
    const int jj = threadIdx.x;
    if (jj >= EMB) return;
    float u = 0.f, v = 0.f;
    for (int k = 0; k < HID; k++) {
        const float w = Wg[(size_t)k * EMB + jj];
        u = fmaf(ln_g[k], w, u);
        v = fmaf(ln_b[k], w, v);
    }
    g_u[jj] = u; g_v[jj] = v;
}

// ============================== edge pipeline ====================================
__global__ void init_kernel(float* __restrict__ out, const float* __restrict__ bias_g)
{
    const int i = blockIdx.x * blockDim.x + threadIdx.x;
    if (i < N_NODES * EMB) out[i] = bias_g[i & (EMB - 1)];
    if (i < N_NODES) { g_m[i] = __int_as_float(0xff800000); g_s[i] = 0.f; }
}

__global__ void edge_max_kernel(const int* __restrict__ src, const int* __restrict__ dst)
{
    const int i = blockIdx.x * blockDim.x + threadIdx.x;
    if (i >= N_EDGES) return;
    float v = g_el[src[i]] + g_er[dst[i]];
    v = v > 0.f ? v : NEG_SLOPE * v;
    g_e[i] = v;
    float* addr = &g_m[dst[i]];
    if (v >= 0.f) atomicMax((int*)addr, __float_as_int(v));
    else          atomicMin((unsigned int*)addr, __float_as_uint(v));
}

__global__ void edge_exp_kernel(const int* __restrict__ dst)
{
    const int i = blockIdx.x * blockDim.x + threadIdx.x;
    if (i >= N_EDGES) return;
    const int d = dst[i];
    const float ex = __expf(g_e[i] - g_m[d]);
    g_e[i] = ex;
    atomicAdd(&g_s[d], ex);
}

__global__ void agg_kernel(const int* __restrict__ src, const int* __restrict__ dst,
                           float* __restrict__ out)
{
    const int w    = (blockIdx.x * blockDim.x + threadIdx.x) >> 5;
    const int lane = threadIdx.x & 31;
    if (w >= N_EDGES) return;
    const int sN = src[w], dN = dst[w];
    const float a  = g_e[w] / g_s[dN];
    const float v0 = g_feat[(size_t)sN * EMB + lane]      * a;
    const float v1 = g_feat[(size_t)sN * EMB + 32 + lane] * a;
    atomicAdd(out + (size_t)dN * EMB + lane,      v0);
    atomicAdd(out + (size_t)dN * EMB + 32 + lane, v1);
}

// =================================================================================
extern "C" void kernel_launch(void* const* d_in, const int* in_sizes, int n_in,
                              void* d_out, int out_size)
{
    const float* features = (const float*)d_in[0];
    const int*   src      = (const int*)  d_in[1];
    const int*   dst      = (const int*)  d_in[2];
    const float* W1       = (const float*)d_in[3];
    const float* b1       = (const float*)d_in[4];
    const float* ln_g     = (const float*)d_in[5];
    const float* ln_b     = (const float*)d_in[6];
    const float* Wg       = (const float*)d_in[7];
    const float* attn_l   = (const float*)d_in[8];
    const float* attn_r   = (const float*)d_in[9];
    const float* bias_g   = (const float*)d_in[10];
    float* out = (float*)d_out;

    prep_w1<<<(IN_DIM * HID + 255) / 256, 256>>>(W1);
    prep_wg<<<(HID * EMB + 255) / 256, 256>>>(Wg, ln_g);
    prep_uv<<<1, 64>>>(Wg, ln_g, ln_b);

    cudaFuncSetAttribute(node_kernel, cudaFuncAttributeMaxDynamicSharedMemorySize, SM_TOTAL);
    node_kernel<<<(N_NODES + 63) / 64, 512, SM_TOTAL>>>(features, b1, attn_l, attn_r);

    init_kernel<<<(N_NODES * EMB + 255) / 256, 256>>>(out, bias_g);
    edge_max_kernel<<<(N_EDGES + 255) / 256, 256>>>(src, dst);
    edge_exp_kernel<<<(N_EDGES + 255) / 256, 256>>>(dst);

    const long long agg_threads = (long long)N_EDGES * 32;
    agg_kernel<<<(int)((agg_threads + 255) / 256), 256>>>(src, dst, out);
}